// round 16
// baseline (speedup 1.0000x reference)
#include <cuda_runtime.h>
#include <cuda_bf16.h>

#define B 32768
#define C 1000
#define NV4 250            // float4 per row
#define NBLK 4096          // engine blocks: 8 rows/block, 1 row/warp
#define NFINB 32           // finisher blocks (trailing)
#define GRID (NBLK + NFINB)

// INVARIANTS at kernel_launch entry (zero at module load, restored each run):
//   g_flag[] == 0, g_cnt == 0, g_hist_done == 0, g_done == 0.
__device__ int      g_flag[NBLK];     // engine block b sets; its finisher clears
__device__ int      g_cnt[C];
__device__ unsigned g_hist_done;      // 32 hist blocks arrive
__device__ float    g_row[B];
__device__ float    g_part[NFINB];
__device__ unsigned g_done;           // finisher ticket

__global__ __launch_bounds__(256) void kl_all_kernel(
    const float* __restrict__ f1,
    const float* __restrict__ f2,
    const int*   __restrict__ label,
    float*       __restrict__ out)
{
    const int tid  = threadIdx.x;
    const int lane = tid & 31;
    const int wid  = tid >> 5;

    if (blockIdx.x >= NBLK) {
        // ================= finisher branch (32 trailing blocks) =============
        __shared__ int   scnt[C];
        __shared__ float swarp[8];
        __shared__ int   s_last;
        const int fb = blockIdx.x - NBLK;

        // wait for our 128 producer blocks + the histogram
        if (tid < 128) {
            int f = fb * 128 + tid;
            while (atomicAdd(&g_flag[f], 0) == 0) { }
        } else if (tid == 128) {
            while (atomicAdd(&g_hist_done, 0) < 32u) { }
        }
        __syncthreads();
        __threadfence();                      // acquire

        // stage g_cnt in smem (coalesced), gather per-row from smem
        #pragma unroll
        for (int k = 0; k < 4; k++) {
            int c = tid + 256 * k;
            if (c < C) scnt[c] = g_cnt[c];
        }
        const int i = fb * 256 + tid;         // int4 index into rows
        float4 v = __ldcg((const float4*)g_row + i);
        int4   L = ((const int4*)label)[i];
        L.x = min(max(L.x, 0), C - 1);
        L.y = min(max(L.y, 0), C - 1);
        L.z = min(max(L.z, 0), C - 1);
        L.w = min(max(L.w, 0), C - 1);
        __syncthreads();

        float s = 0.f;
        s += __fdividef(v.x, (float)max(scnt[L.x], 1));
        s += __fdividef(v.y, (float)max(scnt[L.y], 1));
        s += __fdividef(v.z, (float)max(scnt[L.z], 1));
        s += __fdividef(v.w, (float)max(scnt[L.w], 1));
        #pragma unroll
        for (int o = 16; o; o >>= 1) s += __shfl_xor_sync(0xFFFFFFFFu, s, o);
        if (lane == 0) swarp[wid] = s;

        // restore our slice's flags for the next replay
        if (tid < 128) g_flag[fb * 128 + tid] = 0;
        __syncthreads();

        if (tid == 0) {
            float r = 0.f;
            #pragma unroll
            for (int k = 0; k < 8; k++) r += swarp[k];
            g_part[fb] = r;
            __threadfence();
            unsigned old = atomicAdd(&g_done, 1u);
            s_last = (old == (unsigned)(NFINB - 1)) ? 1 : 0;
        }
        __syncthreads();
        if (!s_last) return;

        // last finisher: deterministic fixed-order sum; restore invariants
        __threadfence();
        if (wid == 0) {
            float r = (lane < NFINB) ? __ldcg(g_part + lane) : 0.f;
            #pragma unroll
            for (int o = 16; o; o >>= 1) r += __shfl_xor_sync(0xFFFFFFFFu, r, o);
            if (lane == 0) out[0] = r * (1.0f / (float)C);
        }
        for (int k = tid; k < C; k += 256) g_cnt[k] = 0;
        if (tid == 0) { g_done = 0u; g_hist_done = 0u; }
        return;
    }

    // ======================= engine (R15 verbatim) ==========================
    // hist prologue: blocks 0..31 cover all 32768 labels, then release-count.
    if (blockIdx.x < 32) {
        int i = blockIdx.x * 256 + tid;
        int4 L = ((const int4*)label)[i];
        atomicAdd(&g_cnt[min(max(L.x, 0), C - 1)], 1);
        atomicAdd(&g_cnt[min(max(L.y, 0), C - 1)], 1);
        atomicAdd(&g_cnt[min(max(L.z, 0), C - 1)], 1);
        atomicAdd(&g_cnt[min(max(L.w, 0), C - 1)], 1);
        __syncthreads();
        if (tid == 0) { __threadfence(); atomicAdd(&g_hist_done, 1u); }
    }

    const int row = blockIdx.x * 8 + wid;
    const float4* p1 = (const float4*)f1 + (size_t)row * NV4;
    const float4* p2 = (const float4*)f2 + (size_t)row * NV4;

    float4 a[8], b[8];
    const float4 NEG = make_float4(-1e30f, -1e30f, -1e30f, -1e30f);
    #pragma unroll
    for (int k = 0; k < 8; k++) {
        int j = lane + 32 * k;
        if (j < NV4) { a[k] = __ldcs(p1 + j); b[k] = __ldcs(p2 + j); }
        else         { a[k] = NEG;            b[k] = NEG;            }
    }

    // pass 1: row maxes (consumes whole row -> ptxas front-batches all loads)
    float m1 = -1e30f, m2 = -1e30f;
    #pragma unroll
    for (int k = 0; k < 8; k++) {
        m1 = fmaxf(m1, fmaxf(fmaxf(a[k].x, a[k].y), fmaxf(a[k].z, a[k].w)));
        m2 = fmaxf(m2, fmaxf(fmaxf(b[k].x, b[k].y), fmaxf(b[k].z, b[k].w)));
    }
    #pragma unroll
    for (int o = 16; o; o >>= 1) {
        m1 = fmaxf(m1, __shfl_xor_sync(0xFFFFFFFFu, m1, o));
        m2 = fmaxf(m2, __shfl_xor_sync(0xFFFFFFFFu, m2, o));
    }

    // pass 2 (registers): s1, s2, wv
    float s1 = 0.f, s2 = 0.f, wv = 0.f;
    #pragma unroll
    for (int k = 0; k < 8; k++) {
        s1 += __expf(a[k].x - m1) + __expf(a[k].y - m1)
            + __expf(a[k].z - m1) + __expf(a[k].w - m1);
        float e;
        e = __expf(b[k].x - m2); s2 += e; wv = fmaf(e, b[k].x - a[k].x, wv);
        e = __expf(b[k].y - m2); s2 += e; wv = fmaf(e, b[k].y - a[k].y, wv);
        e = __expf(b[k].z - m2); s2 += e; wv = fmaf(e, b[k].z - a[k].z, wv);
        e = __expf(b[k].w - m2); s2 += e; wv = fmaf(e, b[k].w - a[k].w, wv);
    }
    #pragma unroll
    for (int o = 16; o; o >>= 1) {
        s1 += __shfl_xor_sync(0xFFFFFFFFu, s1, o);
        s2 += __shfl_xor_sync(0xFFFFFFFFu, s2, o);
        wv += __shfl_xor_sync(0xFFFFFFFFu, wv, o);
    }

    if (lane == 0)
        g_row[row] = wv / s2 + (m1 + __logf(s1)) - (m2 + __logf(s2));

    // release: one flag per engine block (bar.sync HB + tid0 fence => correct)
    __syncthreads();
    if (tid == 0) {
        __threadfence();
        atomicExch(&g_flag[blockIdx.x], 1);
    }
}

extern "C" void kernel_launch(void* const* d_in, const int* in_sizes, int n_in,
                              void* d_out, int out_size)
{
    const float* f1    = (const float*)d_in[0];
    const float* f2    = (const float*)d_in[1];
    const int*   label = (const int*)d_in[2];
    float*       out   = (float*)d_out;

    kl_all_kernel<<<GRID, 256>>>(f1, f2, label, out);
}